// round 4
// baseline (speedup 1.0000x reference)
#include <cuda_runtime.h>
#include <stdint.h>

// SRP map on GB300 — round 4.
//
// maps[f,g] = sum_p x[f, p, tau0[p,g]] (wrapped lags in {0..7}U{504..511}
// -> 16 slots), then per-frame zero-mean + /max.
//
// R4 changes vs R3 (23.0us):
//  * DIAGONAL PAIRS DROPPED (exact): pairs p=13k have tau==0 -> contribute a
//    g-constant, which cancels in the mean subtraction. 144 -> 132 pairs.
//  * pre_pack rebuilt for MLP: 1 thread per tau0 element (270K threads, one
//    coalesced LDG each) + smem byte transpose. Was 4.3us latency-bound.
//  * Normalization fused into gather via fence+atomic last-CTA-arrival:
//    per-CTA partial sum/max in fixed workspace slots (deterministic),
//    counter self-resets for graph replay. Third kernel eliminated.

#define NPAIR   132          // non-diagonal pairs
#define KLEN    512
#define GPTS    2048
#define THREADS 256
#define NCHUNK  33           // 4-pair chunks
#define NSPLIT  8
#define MAXFR   512

// g_tauB[c*2048 + g]: 4 bytes = slot*4 for compact pairs 4c..4c+3 at point g.
__device__ uint32_t g_tauB[NCHUNK * GPTS];
// last-arrival workspace
__device__ float ws_s[MAXFR * NSPLIT];
__device__ float ws_m[MAXFR * NSPLIT];
__device__ int   ws_c[MAXFR];            // zero-initialized; self-resetting

// compact index i (0..131) -> actual pair p, skipping p=13k
__host__ __device__ __forceinline__ int pair_of(int i) { return i + 1 + i / 12; }

// ---------------- tau pack: 1 element per thread ----------------
// block = (chunk c, 64-point tile gb). thread: j = tid>>6 (pair in chunk),
// gl = tid&63. Each thread loads ONE tau0 int (coalesced), smem transpose.
__global__ void __launch_bounds__(256) pre_pack_kernel(const int* __restrict__ tau0) {
    __shared__ uint8_t sm[256];          // [gl][j]
    const int c  = blockIdx.x >> 5;      // 0..32
    const int gb = blockIdx.x & 31;      // 0..31
    const int j  = threadIdx.x >> 6;
    const int gl = threadIdx.x & 63;
    const int p  = pair_of(c * 4 + j);
    const int g  = gb * 64 + gl;
    uint32_t t = (uint32_t)__ldg(&tau0[p * GPTS + g]);
    sm[gl * 4 + j] = (uint8_t)((t & 15u) << 2);   // slot*4
    __syncthreads();
    if (threadIdx.x < 64)
        g_tauB[c * GPTS + gb * 64 + threadIdx.x] =
            ((const uint32_t*)sm)[threadIdx.x];
}

// ---------------- gather + fused normalization ----------------
// CTA: f = blockIdx.x>>3, s = blockIdx.x&7. Thread owns point g = s*256+tid.
__global__ void __launch_bounds__(THREADS) srp_gather_kernel(
    const float* __restrict__ x, float* __restrict__ out)
{
    __shared__ float xsm[NPAIR * 16];    // [r*16 + slot], 8448 B
    __shared__ float red_s[THREADS / 32];
    __shared__ float red_m[THREADS / 32];
    __shared__ float bcast[2];
    __shared__ int   is_last;

    const int f   = blockIdx.x >> 3;
    const int s   = blockIdx.x & 7;
    const int tid = threadIdx.x;

    // ---- Stage the 132x16 used x-values for this frame ----
    const float* xf = x + (size_t)f * (144 * KLEN);
    for (int i = tid; i < NPAIR * 16; i += THREADS) {
        int r  = i >> 4;
        int sl = i & 15;
        int k  = (sl < 8) ? sl : (sl + 496);     // slot -> lag
        xsm[i] = __ldg(&xf[pair_of(r) * KLEN + k]);
    }
    __syncthreads();

    const int g = s * THREADS + tid;
    const uint32_t* tw = g_tauB + g;
    const char* xb = (const char*)xsm;

    float a0 = 0.0f, a1 = 0.0f, a2 = 0.0f, a3 = 0.0f;
#pragma unroll
    for (int c = 0; c < NCHUNK; c++) {
        uint32_t w = __ldg(&tw[c * GPTS]);
        a0 += *(const float*)(xb + (c * 256 +   0) + __byte_perm(w, 0, 0x4440));
        a1 += *(const float*)(xb + (c * 256 +  64) + __byte_perm(w, 0, 0x4441));
        a2 += *(const float*)(xb + (c * 256 + 128) + __byte_perm(w, 0, 0x4442));
        a3 += *(const float*)(xb + (c * 256 + 192) + __byte_perm(w, 0, 0x4443));
    }
    float v = (a0 + a1) + (a2 + a3);

    float* of = out + (size_t)f * GPTS;
    of[g] = v;                                   // unnormalized

    // ---- CTA-local partial sum/max ----
    float ps = v, pm = v;
#pragma unroll
    for (int o = 16; o > 0; o >>= 1) {
        ps += __shfl_xor_sync(0xFFFFFFFFu, ps, o);
        pm = fmaxf(pm, __shfl_xor_sync(0xFFFFFFFFu, pm, o));
    }
    int wid = tid >> 5, lane = tid & 31;
    if (lane == 0) { red_s[wid] = ps; red_m[wid] = pm; }
    __syncthreads();

    if (tid == 0) {
        float cs = 0.0f, cm = -3.0e38f;
#pragma unroll
        for (int w = 0; w < THREADS / 32; w++) {
            cs += red_s[w];
            cm = fmaxf(cm, red_m[w]);
        }
        ws_s[f * NSPLIT + s] = cs;
        ws_m[f * NSPLIT + s] = cm;
        __threadfence();
        int old = atomicAdd(&ws_c[f], 1);
        is_last = (old == NSPLIT - 1) ? 1 : 0;
    }
    __syncthreads();
    if (!is_last) return;

    // ---- Last CTA of this frame: normalize all 2048 points ----
    if (tid == 0) {
        __threadfence();                         // acquire peers' data
        ws_c[f] = 0;                             // reset for next replay
        float tot = 0.0f, mm = -3.0e38f;
#pragma unroll
        for (int k = 0; k < NSPLIT; k++) {       // fixed order: deterministic
            tot += ws_s[f * NSPLIT + k];
            mm = fmaxf(mm, ws_m[f * NSPLIT + k]);
        }
        const float EPS = 1e-12f;
        float mean = tot * (1.0f / (float)GPTS);
        bcast[0] = mean;
        bcast[1] = 1.0f / (mm - mean + EPS);
    }
    __syncthreads();
    const float EPS  = 1e-12f;
    const float mean = bcast[0];
    const float inv  = bcast[1];

#pragma unroll
    for (int e = 0; e < 2; e++) {
        float4 q = *(const float4*)(of + tid * 8 + e * 4);
        q.x = (q.x - mean + EPS) * inv;
        q.y = (q.y - mean + EPS) * inv;
        q.z = (q.z - mean + EPS) * inv;
        q.w = (q.w - mean + EPS) * inv;
        *(float4*)(of + tid * 8 + e * 4) = q;
    }
}

extern "C" void kernel_launch(void* const* d_in, const int* in_sizes, int n_in,
                              void* d_out, int out_size)
{
    const float* x;
    const int*   tau0;
    if (in_sizes[0] == 144 * GPTS) {
        tau0 = (const int*)d_in[0];
        x    = (const float*)d_in[1];
    } else {
        x    = (const float*)d_in[0];
        tau0 = (const int*)d_in[1];
    }

    int nframes = out_size / GPTS;

    pre_pack_kernel<<<NCHUNK * 32, 256>>>(tau0);
    srp_gather_kernel<<<nframes * NSPLIT, THREADS>>>(x, (float*)d_out);
}

// round 7
// speedup vs baseline: 1.1098x; 1.1098x over previous
#include <cuda_runtime.h>
#include <stdint.h>

// SRP map on GB300 — round 5.
//
// maps[f,g] = sum_{k!=l} x[f, k*12+l, tau0[k,l,g]], then per-frame
// zero-mean + /max.  Wrapped lags all in {0..7} U {504..511} -> 16 slots.
//
// R5 structural cuts vs R4 (23.3us, issue+crossbar bound):
//  * PAIR FOLDING (exact): tau0[l,k,g] == -tau0[k,l,g] (TDOA antisymmetry),
//    so stage y[kl][s] = x[k,l,lag(s)] + x[l,k,lag(-s)] and gather over only
//    66 folded pairs. Smem crossbar bytes halved.
//  * 2 FRAMES PER CTA: xsm float2 (f0,f1), LDS.64 + packed add.rn.f32x2.
//    One tau word serves 2 frames. Inner body: PRMT+IADD+LDS.64+FADD2
//    = 4 instr per 4 original gathered values.
//  * LDS.64 conflict-free: lanes share folded-pair row r, differ in slot s;
//    s*8B segments are disjoint within 128B -> 2 cyc/warp-LDS (pure BW).
//  * Diagonal pairs still dropped (g-constant cancels in mean subtraction).

#define KLEN    512
#define GPTS    2048
#define THREADS 256
#define NFOLD   66            // folded pairs (k<l)
#define NROWS   68            // padded to 17 chunks of 4
#define NCHUNK  17
#define NSPLIT  8
#define MAXF2   256           // frame-pairs

// folded pair r -> row indices k*12+l (A) and l*12+k (B)
__constant__ uint8_t c_pairA[NFOLD] = {
  1,2,3,4,5,6,7,8,9,10,11,
  14,15,16,17,18,19,20,21,22,23,
  27,28,29,30,31,32,33,34,35,
  40,41,42,43,44,45,46,47,
  53,54,55,56,57,58,59,
  66,67,68,69,70,71,
  79,80,81,82,83,
  92,93,94,95,
  105,106,107,
  118,119,
  131};
__constant__ uint8_t c_pairB[NFOLD] = {
  12,24,36,48,60,72,84,96,108,120,132,
  25,37,49,61,73,85,97,109,121,133,
  38,50,62,74,86,98,110,122,134,
  51,63,75,87,99,111,123,135,
  64,76,88,100,112,124,136,
  77,89,101,113,125,137,
  90,102,114,126,138,
  103,115,127,139,
  116,128,140,
  129,141,
  142};

// g_tauB[c*2048+g]: 4 bytes = slot*8 (LDS.64 offset) for folded pairs 4c..4c+3.
__device__ uint32_t g_tauB[NCHUNK * GPTS];
// last-arrival workspace (per frame)
__device__ float ws_s[MAXF2 * 2 * NSPLIT];
__device__ float ws_m[MAXF2 * 2 * NSPLIT];
__device__ int   ws_c[MAXF2];          // zero-init; self-resetting

__device__ __forceinline__ int lag_of(int s) { return (s < 8) ? s : (s + 496); }

// ---------------- tau pack ----------------
// block = (chunk c, 64-point tile gb); j = tid>>6 (pair in chunk), gl = tid&63.
__global__ void __launch_bounds__(256) pre_pack_kernel(const int* __restrict__ tau0) {
    __shared__ uint8_t sm[256];
    const int c  = blockIdx.x >> 5;
    const int gb = blockIdx.x & 31;
    const int j  = threadIdx.x >> 6;
    const int gl = threadIdx.x & 63;
    const int pr = c * 4 + j;
    uint8_t b = 0;
    if (pr < NFOLD) {
        uint32_t t = (uint32_t)__ldg(&tau0[(int)c_pairA[pr] * GPTS + gb * 64 + gl]);
        b = (uint8_t)((t & 15u) << 3);          // slot*8
    }
    sm[gl * 4 + j] = b;
    __syncthreads();
    if (threadIdx.x < 64)
        g_tauB[c * GPTS + gb * 64 + threadIdx.x] = ((const uint32_t*)sm)[threadIdx.x];
}

// ---------------- gather + fused normalization ----------------
// CTA: f2 = blockIdx.x>>3 (frame pair), s = blockIdx.x&7.
__global__ void __launch_bounds__(THREADS) srp_gather_kernel(
    const float* __restrict__ x, float* __restrict__ out, int nframes)
{
    __shared__ float2 xsm[NROWS * 16];          // 8704 B, [r*16 + slot]
    __shared__ float red[4][THREADS / 32];
    __shared__ float bcast[4];
    __shared__ int   is_last;

    const int f2  = blockIdx.x >> 3;
    const int s   = blockIdx.x & 7;
    const int tid = threadIdx.x;
    const int f0  = f2 * 2;
    const int f1  = f0 + 1;

    // ---- Stage folded values for both frames ----
    const float* xa = x + (size_t)f0 * (144 * KLEN);
    const float* xb_ = x + (size_t)f1 * (144 * KLEN);
    for (int i = tid; i < NROWS * 16; i += THREADS) {
        int r  = i >> 4;
        int sl = i & 15;
        float2 v = make_float2(0.0f, 0.0f);
        if (r < NFOLD) {
            int ra = (int)c_pairA[r] * KLEN + lag_of(sl);
            int rb = (int)c_pairB[r] * KLEN + lag_of((16 - sl) & 15);
            v.x = __ldg(&xa[ra]) + __ldg(&xa[rb]);
            v.y = __ldg(&xb_[ra]) + __ldg(&xb_[rb]);
        }
        xsm[i] = v;
    }
    __syncthreads();

    const int g = s * THREADS + tid;
    const uint32_t* tw = g_tauB + g;
    const char* xbase = (const char*)xsm;

    unsigned long long a0 = 0ull, a1 = 0ull, a2 = 0ull, a3 = 0ull;
#pragma unroll
    for (int c = 0; c < NCHUNK; c++) {
        uint32_t w = __ldg(&tw[c * GPTS]);
        const char* cb = xbase + c * 512;
        unsigned long long v0 = *(const unsigned long long*)(cb +   0 + __byte_perm(w, 0, 0x4440));
        unsigned long long v1 = *(const unsigned long long*)(cb + 128 + __byte_perm(w, 0, 0x4441));
        unsigned long long v2 = *(const unsigned long long*)(cb + 256 + __byte_perm(w, 0, 0x4442));
        unsigned long long v3 = *(const unsigned long long*)(cb + 384 + __byte_perm(w, 0, 0x4443));
        asm("add.rn.f32x2 %0, %0, %1;" : "+l"(a0) : "l"(v0));
        asm("add.rn.f32x2 %0, %0, %1;" : "+l"(a1) : "l"(v1));
        asm("add.rn.f32x2 %0, %0, %1;" : "+l"(a2) : "l"(v2));
        asm("add.rn.f32x2 %0, %0, %1;" : "+l"(a3) : "l"(v3));
    }

    float2 t0 = *(float2*)&a0, t1 = *(float2*)&a1;
    float2 t2 = *(float2*)&a2, t3 = *(float2*)&a3;
    float v0 = (t0.x + t1.x) + (t2.x + t3.x);   // frame f0, point g
    float v1 = (t0.y + t1.y) + (t2.y + t3.y);   // frame f1, point g

    float* o0 = out + (size_t)f0 * GPTS;
    float* o1 = out + (size_t)f1 * GPTS;
    o0[g] = v0;
    o1[g] = v1;

    // ---- CTA-local partial sum/max for both frames ----
    float s0 = v0, m0 = v0, s1 = v1, m1 = v1;
#pragma unroll
    for (int o = 16; o > 0; o >>= 1) {
        s0 += __shfl_xor_sync(0xFFFFFFFFu, s0, o);
        m0 = fmaxf(m0, __shfl_xor_sync(0xFFFFFFFFu, m0, o));
        s1 += __shfl_xor_sync(0xFFFFFFFFu, s1, o);
        m1 = fmaxf(m1, __shfl_xor_sync(0xFFFFFFFFu, m1, o));
    }
    int wid = tid >> 5, lane = tid & 31;
    if (lane == 0) {
        red[0][wid] = s0; red[1][wid] = m0;
        red[2][wid] = s1; red[3][wid] = m1;
    }
    __syncthreads();

    if (tid == 0) {
        float cs0 = 0.f, cm0 = -3.0e38f, cs1 = 0.f, cm1 = -3.0e38f;
#pragma unroll
        for (int w = 0; w < THREADS / 32; w++) {
            cs0 += red[0][w]; cm0 = fmaxf(cm0, red[1][w]);
            cs1 += red[2][w]; cm1 = fmaxf(cm1, red[3][w]);
        }
        ws_s[(f0 * NSPLIT) + s] = cs0;  ws_m[(f0 * NSPLIT) + s] = cm0;
        ws_s[(f1 * NSPLIT) + s] = cs1;  ws_m[(f1 * NSPLIT) + s] = cm1;
        __threadfence();
        int old = atomicAdd(&ws_c[f2], 1);
        is_last = (old == NSPLIT - 1) ? 1 : 0;
    }
    __syncthreads();
    if (!is_last) return;

    // ---- Last CTA of this frame pair: normalize both frames ----
    if (tid == 0) {
        __threadfence();
        ws_c[f2] = 0;                           // reset for next graph replay
        const float EPS = 1e-12f;
#pragma unroll
        for (int fr = 0; fr < 2; fr++) {
            int f = f0 + fr;
            float tot = 0.f, mm = -3.0e38f;
#pragma unroll
            for (int k = 0; k < NSPLIT; k++) {  // fixed order: deterministic
                tot += ws_s[f * NSPLIT + k];
                mm = fmaxf(mm, ws_m[f * NSPLIT + k]);
            }
            float mean = tot * (1.0f / (float)GPTS);
            bcast[fr * 2]     = mean;
            bcast[fr * 2 + 1] = 1.0f / (mm - mean + EPS);
        }
    }
    __syncthreads();

    const float EPS = 1e-12f;
#pragma unroll
    for (int fr = 0; fr < 2; fr++) {
        float* of   = (fr == 0) ? o0 : o1;
        float mean  = bcast[fr * 2];
        float inv   = bcast[fr * 2 + 1];
#pragma unroll
        for (int e = 0; e < 2; e++) {
            float4 q = *(const float4*)(of + tid * 8 + e * 4);
            q.x = (q.x - mean + EPS) * inv;
            q.y = (q.y - mean + EPS) * inv;
            q.z = (q.z - mean + EPS) * inv;
            q.w = (q.w - mean + EPS) * inv;
            *(float4*)(of + tid * 8 + e * 4) = q;
        }
    }
}

extern "C" void kernel_launch(void* const* d_in, const int* in_sizes, int n_in,
                              void* d_out, int out_size)
{
    const float* x;
    const int*   tau0;
    if (in_sizes[0] == 144 * GPTS) {
        tau0 = (const int*)d_in[0];
        x    = (const float*)d_in[1];
    } else {
        x    = (const float*)d_in[0];
        tau0 = (const int*)d_in[1];
    }

    int nframes = out_size / GPTS;      // 256
    int nf2     = nframes / 2;          // 128 frame pairs

    pre_pack_kernel<<<NCHUNK * 32, 256>>>(tau0);
    srp_gather_kernel<<<nf2 * NSPLIT, THREADS>>>(x, (float*)d_out, nframes);
}